// round 16
// baseline (speedup 1.0000x reference)
#include <cuda_runtime.h>
#include <cstdint>

// Problem constants
#define NROWS 65536
#define DDIM  64
#define KEMB  8192

#define BM 128
#define BN 128
#define NTILES (KEMB / BN)      // 64
#define NTHREADS 256            // 8 warps: 4 row-groups x 2 col-groups
#define NCTAS (NROWS / BM)      // 512
#define CAPT 64                 // per-thread candidate capacity

// Output layout (flattened fp32): quantized | vq_loss | commit_loss | idx
#define OUT_LOSS   (NROWS * DDIM)
#define OUT_IDX    (NROWS * DDIM + 2)
#define NPARTIAL   1024

// pass-1 smem offsets
#define SM_B0    0               // 16384: hi bf16x2 words, swizzled
#define SM_B1    16384
#define SM_Z     32768           // 34816: 128 x 68 f32 (padded)
#define SM_SABS  67584           // 512
#define SM_RVV   68096           // 512 (cg merge of bs)
#define SMEM_TOTAL 68608

typedef unsigned long long ull;

// scratch
__device__ float          g_esq[KEMB];
__device__ uint32_t       g_ebf[KEMB * 32];   // hi bf16x2 words, swizzled per row
__device__ int            g_idx[NROWS];
__device__ float          g_partial[NPARTIAL];
__device__ unsigned int   g_maxe;
__device__ unsigned short g_clist[(size_t)NCTAS * CAPT * NTHREADS];  // 16 MB
__device__ float          g_cacc[(size_t)NCTAS * CAPT * NTHREADS];   // 32 MB
__device__ unsigned int   g_ccnt[NCTAS * NTHREADS];                  // 512 KB
__device__ float          g_thr[NROWS];                              // final thresholds

// ---------------------------------------------------------------------------
__device__ __forceinline__ uint32_t pack_bf16x2(float lo, float hi) {
    uint32_t d;
    asm("cvt.rn.bf16x2.f32 %0, %1, %2;" : "=r"(d) : "f"(hi), "f"(lo));
    return d;
}
__device__ __forceinline__ void mma16(float c[4], const uint32_t a[4],
                                      uint32_t b0, uint32_t b1) {
    asm volatile(
        "mma.sync.aligned.m16n8k16.row.col.f32.bf16.bf16.f32 "
        "{%0,%1,%2,%3},{%4,%5,%6,%7},{%8,%9},{%0,%1,%2,%3};"
        : "+f"(c[0]), "+f"(c[1]), "+f"(c[2]), "+f"(c[3])
        : "r"(a[0]), "r"(a[1]), "r"(a[2]), "r"(a[3]), "r"(b0), "r"(b1));
}
__device__ __forceinline__ uint32_t smem_u32(const void* p) {
    uint32_t a;
    asm("{ .reg .u64 t; cvta.to.shared.u64 t, %1; cvt.u32.u64 %0, t; }"
        : "=r"(a) : "l"(p));
    return a;
}
__device__ __forceinline__ void cp16(uint32_t dst, const void* src) {
    asm volatile("cp.async.cg.shared.global [%0], [%1], 16;"
                 :: "r"(dst), "l"(src) : "memory");
}
#define CP_COMMIT() asm volatile("cp.async.commit_group;" ::: "memory")
#define CP_WAIT1()  asm volatile("cp.async.wait_group 1;" ::: "memory")
#define CP_WAIT0()  asm volatile("cp.async.wait_group 0;" ::: "memory")

// ---------------------------------------------------------------------------
// Kernel 1a: e_sq (exact sequential fp32 chain) + global max|e|
// ---------------------------------------------------------------------------
__global__ void esq_kernel(const float* __restrict__ E) {
    int k = blockIdx.x * blockDim.x + threadIdx.x;
    if (k < KEMB) {
        const float* row = E + k * DDIM;
        float s = 0.f, m = 0.f;
#pragma unroll
        for (int d = 0; d < DDIM; d++) {
            float v = row[d];
            s = fmaf(v, v, s);
            m = fmaxf(m, fabsf(v));
        }
        g_esq[k] = s;
        atomicMax(&g_maxe, __float_as_uint(m));   // positive floats: bit-monotone
    }
}

// ---------------------------------------------------------------------------
// Kernel 1b: E -> hi bf16x2 words, row-swizzled (word idx kw ^ ((n&7)<<2))
// ---------------------------------------------------------------------------
__global__ void esplit_kernel(const float* __restrict__ E) {
    int n = blockIdx.x * blockDim.x + threadIdx.x;
    if (n < KEMB) {
        const float4* sp = reinterpret_cast<const float4*>(E + (size_t)n * DDIM);
        uint32_t* row = g_ebf + (size_t)n * 32;
        const int sw = (n & 7) << 2;
#pragma unroll
        for (int q = 0; q < 16; q++) {
            float4 v = sp[q];
            int kw = q * 2;
            row[kw ^ sw]       = pack_bf16x2(v.x, v.y);
            row[(kw + 1) ^ sw] = pack_bf16x2(v.z, v.w);
        }
    }
}

// ---------------------------------------------------------------------------
// Kernel 2: PASS 1 — hh-only bf16 screen; candidate lists with acc values;
// writes final per-row threshold g_thr
// ---------------------------------------------------------------------------
__global__ __launch_bounds__(NTHREADS, 2) void vq_pass1(
    const float* __restrict__ Z)
{
    extern __shared__ __align__(16) char sm[];
    float* Zs   = reinterpret_cast<float*>(sm + SM_Z);
    float* SABS = reinterpret_cast<float*>(sm + SM_SABS);
    float* RVV  = reinterpret_cast<float*>(sm + SM_RVV);
    const uint32_t smb = smem_u32(sm);

    const int tid  = threadIdx.x;
    const int lane = tid & 31;
    const int warp = tid >> 5;
    const int cg   = warp & 1;
    const int rw   = warp >> 1;
    const int g    = lane >> 2;
    const int tq   = lane & 3;
    const int rowBase = blockIdx.x * BM;

    const char* EBF = reinterpret_cast<const char*>(g_ebf);

    // cp.async: B tile 0 and 1 (16 KB each)
#pragma unroll
    for (int i = 0; i < 4; i++) {
        int c = tid + i * 256;
        cp16(smb + SM_B0 + c * 16, EBF + c * 16);
    }
    CP_COMMIT();
#pragma unroll
    for (int i = 0; i < 4; i++) {
        int c = tid + i * 256;
        cp16(smb + SM_B1 + c * 16, EBF + 16384 + c * 16);
    }
    CP_COMMIT();

    // stage Z tile (pad-68 rows)
    {
        const float4* zp = reinterpret_cast<const float4*>(Z + (size_t)rowBase * DDIM);
#pragma unroll
        for (int i = 0; i < 8; i++) {
            int c = tid + i * 256;
            int m = c >> 4, kc = c & 15;
            float4 v = zp[c];
            *reinterpret_cast<float4*>(&Zs[m * 68 + kc * 4]) = v;
        }
    }
    __syncthreads();

    // sabs per row
    if (tid < BM) {
        float a = 0.f;
#pragma unroll
        for (int d = 0; d < DDIM; d++) a += fabsf(Zs[tid * 68 + d]);
        SABS[tid] = a;
    }

    // A fragments (hi bf16 only)
    uint32_t ah[2][4][4];
#pragma unroll
    for (int mf = 0; mf < 2; mf++) {
        const int r0 = rw * 32 + mf * 16 + g;
#pragma unroll
        for (int kc = 0; kc < 4; kc++) {
            const int k0 = kc * 16 + 2 * tq;
            float2 p0 = *reinterpret_cast<const float2*>(&Zs[r0 * 68 + k0]);
            float2 p1 = *reinterpret_cast<const float2*>(&Zs[(r0 + 8) * 68 + k0]);
            float2 p2 = *reinterpret_cast<const float2*>(&Zs[r0 * 68 + k0 + 8]);
            float2 p3 = *reinterpret_cast<const float2*>(&Zs[(r0 + 8) * 68 + k0 + 8]);
            ah[mf][kc][0] = pack_bf16x2(p0.x, p0.y);
            ah[mf][kc][1] = pack_bf16x2(p1.x, p1.y);
            ah[mf][kc][2] = pack_bf16x2(p2.x, p2.y);
            ah[mf][kc][3] = pack_bf16x2(p3.x, p3.y);
        }
    }
    CP_WAIT1();
    __syncthreads();

    // tau in acc-space: 2x bf16-hh dot bound + es-range + fp32 ulps, all covered
    const float maxe = __uint_as_float(g_maxe);
    float tauS[4], bs[4];
#pragma unroll
    for (int ri = 0; ri < 4; ri++) {
        int rowL = rw * 32 + (ri >> 1) * 16 + g + (ri & 1) * 8;
        tauS[ri] = fmaf(0.008f * maxe, SABS[rowL], 1.0e-4f);
        bs[ri]   = -3.4e38f;
    }

    const int swg = g << 2;
    unsigned cnt = 0;
    unsigned short* clist = g_clist + (size_t)blockIdx.x * CAPT * NTHREADS + tid;
    float*          cacc  = g_cacc  + (size_t)blockIdx.x * CAPT * NTHREADS + tid;

    for (int t = 0; t < NTILES; t++) {
        if (t) {
            if (t >= NTILES - 1) { CP_WAIT0(); } else { CP_WAIT1(); }
            __syncthreads();
        }

        const uint32_t* Bbuf = reinterpret_cast<const uint32_t*>(
            sm + ((t & 1) ? SM_B1 : SM_B0));

        float acc[2][8][4];
#pragma unroll
        for (int mf = 0; mf < 2; mf++)
#pragma unroll
            for (int nf = 0; nf < 8; nf++)
#pragma unroll
                for (int j = 0; j < 4; j++) acc[mf][nf][j] = 0.f;

#pragma unroll
        for (int kc = 0; kc < 4; kc++) {
            const int ki = (kc * 8 + tq) ^ swg;
#pragma unroll
            for (int nf = 0; nf < 8; nf++) {
                const uint32_t* rowp = Bbuf + (cg * 64 + nf * 8 + g) * 32;
                uint32_t b0 = rowp[ki];
                uint32_t b1 = rowp[ki ^ 4];
#pragma unroll
                for (int mf = 0; mf < 2; mf++)
                    mma16(acc[mf][nf], ah[mf][kc], b0, b1);
            }
        }

        // epilogue: running row-max of acc (tq-merged), append candidates+acc
#pragma unroll
        for (int ri = 0; ri < 4; ri++) {
            const int mf = ri >> 1, jb = (ri & 1) * 2;
            float tmax = acc[mf][0][jb];
            tmax = fmaxf(tmax, acc[mf][0][jb + 1]);
#pragma unroll
            for (int nf = 1; nf < 8; nf++) {
                tmax = fmaxf(tmax, acc[mf][nf][jb]);
                tmax = fmaxf(tmax, acc[mf][nf][jb + 1]);
            }
            tmax = fmaxf(tmax, __shfl_xor_sync(0xFFFFFFFFu, tmax, 1));
            tmax = fmaxf(tmax, __shfl_xor_sync(0xFFFFFFFFu, tmax, 2));
            bs[ri] = fmaxf(bs[ri], tmax);
            const float thr = bs[ri] - tauS[ri];
            unsigned m = 0;
#pragma unroll
            for (int nf = 0; nf < 8; nf++) {
                if (acc[mf][nf][jb]     > thr) m |= 1u << (nf * 2);
                if (acc[mf][nf][jb + 1] > thr) m |= 1u << (nf * 2 + 1);
            }
            while (m) {
                int q = __ffs(m) - 1;
                m &= m - 1;
                float av = acc[mf][q >> 1][jb + (q & 1)];
                if (cnt < CAPT) {
                    clist[(size_t)cnt * NTHREADS] =
                        (unsigned short)((t << 6) | (ri << 4) | q);
                    cacc[(size_t)cnt * NTHREADS] = av;
                }
                cnt++;
            }
        }

        __syncthreads();

        if (t + 2 < NTILES) {
            const uint32_t dbase = smb + ((t & 1) ? SM_B1 : SM_B0);
            const char* src = EBF + (size_t)(t + 2) * 16384;
#pragma unroll
            for (int i = 0; i < 4; i++) {
                int c = tid + i * 256;
                cp16(dbase + c * 16, src + c * 16);
            }
            CP_COMMIT();
        }
    }
    g_ccnt[blockIdx.x * NTHREADS + tid] = cnt;

    // final per-row threshold: merge bs across the two cg warps
    if (tq == 0 && cg == 0) {
#pragma unroll
        for (int ri = 0; ri < 4; ri++) {
            int rowL = rw * 32 + (ri >> 1) * 16 + g + (ri & 1) * 8;
            RVV[rowL] = bs[ri];
        }
    }
    __syncthreads();
    if (tq == 0 && cg == 1) {
#pragma unroll
        for (int ri = 0; ri < 4; ri++) {
            int rowL = rw * 32 + (ri >> 1) * 16 + g + (ri & 1) * 8;
            g_thr[rowBase + rowL] = fmaxf(bs[ri], RVV[rowL]) - tauS[ri];
        }
    }
}

// ---------------------------------------------------------------------------
// Kernel 3: PASS 2 — filter by final threshold, exact rescoring (R1 chain),
// per-row argmin via packed (d2,col) smem atomicMin (tie -> lowest col)
// ---------------------------------------------------------------------------
__global__ __launch_bounds__(256) void vq_pass2(
    const float* __restrict__ Z, const float* __restrict__ E)
{
    __shared__ float Zsh[BM * DDIM];     // 32 KB
    __shared__ float ZSQ2[BM];
    __shared__ float THR[BM];
    __shared__ ull   best[BM];

    const int b   = blockIdx.x;
    const int tid = threadIdx.x;
    const int warp = tid >> 5;
    const int cg   = warp & 1;
    const int rw   = warp >> 1;
    const int g    = (tid & 31) >> 2;
    const int tq   = tid & 3;

    // stage Z slab
    {
        const float4* zp = reinterpret_cast<const float4*>(Z + (size_t)b * BM * DDIM);
#pragma unroll
        for (int i = 0; i < 8; i++) {
            int c = tid + i * 256;
            reinterpret_cast<float4*>(Zsh)[c] = zp[c];
        }
    }
    if (tid < BM) {
        best[tid] = 0xFFFFFFFFFFFFFFFFull;
        THR[tid]  = g_thr[b * BM + tid];
    }
    __syncthreads();

    if (tid < BM) {
        float s = 0.f;
#pragma unroll
        for (int d = 0; d < DDIM; d++) {
            float v = Zsh[tid * DDIM + d];
            s = fmaf(v, v, s);
        }
        ZSQ2[tid] = s;
    }
    __syncthreads();

    const unsigned cnt = g_ccnt[b * NTHREADS + tid];
    const unsigned short* clist = g_clist + (size_t)b * CAPT * NTHREADS + tid;
    const float*          cacc  = g_cacc  + (size_t)b * CAPT * NTHREADS + tid;

    if (cnt <= CAPT) {
        for (unsigned s = 0; s < cnt; s++) {
            unsigned e = clist[(size_t)s * NTHREADS];
            float   av = cacc[(size_t)s * NTHREADS];
            int ri = (e >> 4) & 3;
            int rowL = rw * 32 + (ri >> 1) * 16 + g + (ri & 1) * 8;
            if (av > THR[rowL]) {
                int t  = e >> 6;
                int q  = e & 15;
                int col  = t * BN + cg * 64 + (q >> 1) * 8 + 2 * tq + (q & 1);
                const float* zr = Zsh + rowL * DDIM;
                const float4* ep = reinterpret_cast<const float4*>(
                    E + (size_t)col * DDIM);
                float dot = 0.f;
#pragma unroll
                for (int qq = 0; qq < 16; qq++) {
                    float4 e4 = ep[qq];
                    dot = fmaf(zr[qq * 4 + 0], e4.x, dot);
                    dot = fmaf(zr[qq * 4 + 1], e4.y, dot);
                    dot = fmaf(zr[qq * 4 + 2], e4.z, dot);
                    dot = fmaf(zr[qq * 4 + 3], e4.w, dot);
                }
                float tt = fmaf(-2.0f, dot, ZSQ2[rowL]);
                float d2 = tt + g_esq[col];                 // exact R1 chain
                ull pk = ((ull)__float_as_uint(d2) << 32) | (unsigned)col;
                atomicMin(&best[rowL], pk);
            }
        }
    } else {
        // overflow fallback: exact scan of this thread's 4 rows (never expected)
#pragma unroll
        for (int ri = 0; ri < 4; ri++) {
            int rowL = rw * 32 + (ri >> 1) * 16 + g + (ri & 1) * 8;
            const float* zr = Zsh + rowL * DDIM;
            for (int col = 0; col < KEMB; col++) {
                const float4* ep = reinterpret_cast<const float4*>(
                    E + (size_t)col * DDIM);
                float dot = 0.f;
#pragma unroll
                for (int qq = 0; qq < 16; qq++) {
                    float4 e4 = ep[qq];
                    dot = fmaf(zr[qq * 4 + 0], e4.x, dot);
                    dot = fmaf(zr[qq * 4 + 1], e4.y, dot);
                    dot = fmaf(zr[qq * 4 + 2], e4.z, dot);
                    dot = fmaf(zr[qq * 4 + 3], e4.w, dot);
                }
                float tt = fmaf(-2.0f, dot, ZSQ2[rowL]);
                float d2 = tt + g_esq[col];
                ull pk = ((ull)__float_as_uint(d2) << 32) | (unsigned)col;
                atomicMin(&best[rowL], pk);
            }
        }
    }
    __syncthreads();
    if (tid < BM) g_idx[b * BM + tid] = (int)(unsigned)best[tid];
}

// ---------------------------------------------------------------------------
// Kernel 4: gather + partial loss + index-as-float
// ---------------------------------------------------------------------------
__global__ __launch_bounds__(256) void gather_loss_kernel(
    const float* __restrict__ Z, const float* __restrict__ E,
    float* __restrict__ out)
{
    __shared__ float red[256];
    const int tid  = threadIdx.x;
    const int gtid = blockIdx.x * blockDim.x + tid;

    float lsum = 0.f;
    const float4* Z4 = reinterpret_cast<const float4*>(Z);
    float4* O4 = reinterpret_cast<float4*>(out);

#pragma unroll
    for (int j = 0; j < 4; j++) {
        int f   = gtid * 4 + j;
        int row = f >> 4;
        int dc  = (f & 15);
        int idx = g_idx[row];
        const float4* E4 = reinterpret_cast<const float4*>(E + (size_t)idx * DDIM);
        float4 q = E4[dc];
        float4 z = Z4[f];
        O4[f] = q;
        float dx = z.x - q.x, dy = z.y - q.y, dz = z.z - q.z, dw = z.w - q.w;
        lsum += dx * dx + dy * dy + dz * dz + dw * dw;
    }

    if (gtid < NROWS) out[OUT_IDX + gtid] = (float)g_idx[gtid];

    red[tid] = lsum;
    __syncthreads();
    for (int s = 128; s > 0; s >>= 1) {
        if (tid < s) red[tid] += red[tid + s];
        __syncthreads();
    }
    if (tid == 0) g_partial[blockIdx.x] = red[0];
}

// ---------------------------------------------------------------------------
// Kernel 5: finalize losses
// ---------------------------------------------------------------------------
__global__ __launch_bounds__(512) void finalize_kernel(float* __restrict__ out) {
    __shared__ float red[512];
    int tid = threadIdx.x;
    red[tid] = g_partial[tid] + g_partial[tid + 512];
    __syncthreads();
    for (int s = 256; s > 0; s >>= 1) {
        if (tid < s) red[tid] += red[tid + s];
        __syncthreads();
    }
    if (tid == 0) {
        float loss = red[0] * (1.0f / (float)(NROWS * DDIM)); // N*D = 2^22, exact
        out[OUT_LOSS + 0] = loss;
        out[OUT_LOSS + 1] = loss;
    }
}

// ---------------------------------------------------------------------------
extern "C" void kernel_launch(void* const* d_in, const int* in_sizes, int n_in,
                              void* d_out, int out_size)
{
    const float* Z = (const float*)d_in[0];
    const float* E = (const float*)d_in[1];
    if (n_in >= 2 && in_sizes[0] == KEMB * DDIM && in_sizes[1] == NROWS * DDIM) {
        const float* t = Z; Z = E; E = t;
    }
    float* out = (float*)d_out;

    cudaFuncSetAttribute(vq_pass1,
                         cudaFuncAttributeMaxDynamicSharedMemorySize, SMEM_TOTAL);

    esq_kernel<<<KEMB / 256, 256>>>(E);
    esplit_kernel<<<KEMB / 256, 256>>>(E);
    vq_pass1<<<NCTAS, NTHREADS, SMEM_TOTAL>>>(Z);
    vq_pass2<<<NCTAS, 256>>>(Z, E);
    gather_loss_kernel<<<NPARTIAL, 256>>>(Z, E, out);
    finalize_kernel<<<1, 512>>>(out);
}

// round 17
// speedup vs baseline: 1.1687x; 1.1687x over previous
#include <cuda_runtime.h>
#include <cstdint>

// Problem constants
#define NROWS 65536
#define DDIM  64
#define KEMB  8192

#define BM 128
#define BN 128
#define NTILES (KEMB / BN)      // 64
#define NTHREADS 256            // 8 warps: 4 row-groups x 2 col-groups
#define NCTAS (NROWS / BM)      // 512
#define CAPT 64                 // per-thread candidate capacity

// Output layout (flattened fp32): quantized | vq_loss | commit_loss | idx
#define OUT_LOSS   (NROWS * DDIM)
#define OUT_IDX    (NROWS * DDIM + 2)
#define NPARTIAL   1024

// pass-1 smem offsets
#define SM_B0    0               // 16384: hi bf16x2 words, swizzled
#define SM_B1    16384
#define SM_Z     32768           // 34816: 128 x 68 f32 (padded)
#define SM_SABS  67584           // 512
#define SM_RVV   68096           // 512 (cg merge of bs)
#define SMEM_TOTAL 68608

typedef unsigned long long ull;

// scratch
__device__ float          g_esq[KEMB];
__device__ uint32_t       g_ebf[KEMB * 32];   // hi bf16x2 words, swizzled per row
__device__ int            g_idx[NROWS];
__device__ float          g_partial[NPARTIAL];
__device__ unsigned int   g_maxe;
__device__ unsigned short g_clist[(size_t)NCTAS * CAPT * NTHREADS];  // 16 MB
__device__ float          g_cacc[(size_t)NCTAS * CAPT * NTHREADS];   // 32 MB
__device__ unsigned int   g_ccnt[NCTAS * NTHREADS];                  // 512 KB
__device__ float          g_thr[NROWS];                              // final thresholds

// ---------------------------------------------------------------------------
__device__ __forceinline__ uint32_t pack_bf16x2(float lo, float hi) {
    uint32_t d;
    asm("cvt.rn.bf16x2.f32 %0, %1, %2;" : "=r"(d) : "f"(hi), "f"(lo));
    return d;
}
__device__ __forceinline__ void mma16(float c[4], const uint32_t a[4],
                                      uint32_t b0, uint32_t b1) {
    asm volatile(
        "mma.sync.aligned.m16n8k16.row.col.f32.bf16.bf16.f32 "
        "{%0,%1,%2,%3},{%4,%5,%6,%7},{%8,%9},{%0,%1,%2,%3};"
        : "+f"(c[0]), "+f"(c[1]), "+f"(c[2]), "+f"(c[3])
        : "r"(a[0]), "r"(a[1]), "r"(a[2]), "r"(a[3]), "r"(b0), "r"(b1));
}
__device__ __forceinline__ uint32_t smem_u32(const void* p) {
    uint32_t a;
    asm("{ .reg .u64 t; cvta.to.shared.u64 t, %1; cvt.u32.u64 %0, t; }"
        : "=r"(a) : "l"(p));
    return a;
}
__device__ __forceinline__ void cp16(uint32_t dst, const void* src) {
    asm volatile("cp.async.cg.shared.global [%0], [%1], 16;"
                 :: "r"(dst), "l"(src) : "memory");
}
#define CP_COMMIT() asm volatile("cp.async.commit_group;" ::: "memory")
#define CP_WAIT1()  asm volatile("cp.async.wait_group 1;" ::: "memory")
#define CP_WAIT0()  asm volatile("cp.async.wait_group 0;" ::: "memory")

// ---------------------------------------------------------------------------
// Kernel 1a: e_sq (exact sequential fp32 chain) + global max|e|
// ---------------------------------------------------------------------------
__global__ void esq_kernel(const float* __restrict__ E) {
    int k = blockIdx.x * blockDim.x + threadIdx.x;
    if (k < KEMB) {
        const float* row = E + k * DDIM;
        float s = 0.f, m = 0.f;
#pragma unroll
        for (int d = 0; d < DDIM; d++) {
            float v = row[d];
            s = fmaf(v, v, s);
            m = fmaxf(m, fabsf(v));
        }
        g_esq[k] = s;
        atomicMax(&g_maxe, __float_as_uint(m));   // positive floats: bit-monotone
    }
}

// ---------------------------------------------------------------------------
// Kernel 1b: E -> hi bf16x2 words, row-swizzled (word idx kw ^ ((n&7)<<2))
// ---------------------------------------------------------------------------
__global__ void esplit_kernel(const float* __restrict__ E) {
    int n = blockIdx.x * blockDim.x + threadIdx.x;
    if (n < KEMB) {
        const float4* sp = reinterpret_cast<const float4*>(E + (size_t)n * DDIM);
        uint32_t* row = g_ebf + (size_t)n * 32;
        const int sw = (n & 7) << 2;
#pragma unroll
        for (int q = 0; q < 16; q++) {
            float4 v = sp[q];
            int kw = q * 2;
            row[kw ^ sw]       = pack_bf16x2(v.x, v.y);
            row[(kw + 1) ^ sw] = pack_bf16x2(v.z, v.w);
        }
    }
}

// ---------------------------------------------------------------------------
// Kernel 2: PASS 1 — hh-only bf16 screen; candidate lists + acc values;
// statically-indexed predicated appends (no dynamic reg indexing!)
// ---------------------------------------------------------------------------
__global__ __launch_bounds__(NTHREADS, 2) void vq_pass1(
    const float* __restrict__ Z)
{
    extern __shared__ __align__(16) char sm[];
    float* Zs   = reinterpret_cast<float*>(sm + SM_Z);
    float* SABS = reinterpret_cast<float*>(sm + SM_SABS);
    float* RVV  = reinterpret_cast<float*>(sm + SM_RVV);
    const uint32_t smb = smem_u32(sm);

    const int tid  = threadIdx.x;
    const int lane = tid & 31;
    const int warp = tid >> 5;
    const int cg   = warp & 1;
    const int rw   = warp >> 1;
    const int g    = lane >> 2;
    const int tq   = lane & 3;
    const int rowBase = blockIdx.x * BM;

    const char* EBF = reinterpret_cast<const char*>(g_ebf);

    // cp.async: B tile 0 and 1 (16 KB each)
#pragma unroll
    for (int i = 0; i < 4; i++) {
        int c = tid + i * 256;
        cp16(smb + SM_B0 + c * 16, EBF + c * 16);
    }
    CP_COMMIT();
#pragma unroll
    for (int i = 0; i < 4; i++) {
        int c = tid + i * 256;
        cp16(smb + SM_B1 + c * 16, EBF + 16384 + c * 16);
    }
    CP_COMMIT();

    // stage Z tile (pad-68 rows)
    {
        const float4* zp = reinterpret_cast<const float4*>(Z + (size_t)rowBase * DDIM);
#pragma unroll
        for (int i = 0; i < 8; i++) {
            int c = tid + i * 256;
            int m = c >> 4, kc = c & 15;
            float4 v = zp[c];
            *reinterpret_cast<float4*>(&Zs[m * 68 + kc * 4]) = v;
        }
    }
    __syncthreads();

    // sabs per row
    if (tid < BM) {
        float a = 0.f;
#pragma unroll
        for (int d = 0; d < DDIM; d++) a += fabsf(Zs[tid * 68 + d]);
        SABS[tid] = a;
    }

    // A fragments (hi bf16 only)
    uint32_t ah[2][4][4];
#pragma unroll
    for (int mf = 0; mf < 2; mf++) {
        const int r0 = rw * 32 + mf * 16 + g;
#pragma unroll
        for (int kc = 0; kc < 4; kc++) {
            const int k0 = kc * 16 + 2 * tq;
            float2 p0 = *reinterpret_cast<const float2*>(&Zs[r0 * 68 + k0]);
            float2 p1 = *reinterpret_cast<const float2*>(&Zs[(r0 + 8) * 68 + k0]);
            float2 p2 = *reinterpret_cast<const float2*>(&Zs[r0 * 68 + k0 + 8]);
            float2 p3 = *reinterpret_cast<const float2*>(&Zs[(r0 + 8) * 68 + k0 + 8]);
            ah[mf][kc][0] = pack_bf16x2(p0.x, p0.y);
            ah[mf][kc][1] = pack_bf16x2(p1.x, p1.y);
            ah[mf][kc][2] = pack_bf16x2(p2.x, p2.y);
            ah[mf][kc][3] = pack_bf16x2(p3.x, p3.y);
        }
    }
    CP_WAIT1();
    __syncthreads();

    // tau in acc-space: 2x bf16-hh dot bound + es-range + fp32 ulps, all covered
    const float maxe = __uint_as_float(g_maxe);
    float tauS[4], bs[4];
#pragma unroll
    for (int ri = 0; ri < 4; ri++) {
        int rowL = rw * 32 + (ri >> 1) * 16 + g + (ri & 1) * 8;
        tauS[ri] = fmaf(0.008f * maxe, SABS[rowL], 1.0e-4f);
        bs[ri]   = -3.4e38f;
    }

    const int swg = g << 2;
    unsigned cnt = 0;
    unsigned short* clist = g_clist + (size_t)blockIdx.x * CAPT * NTHREADS + tid;
    float*          cacc  = g_cacc  + (size_t)blockIdx.x * CAPT * NTHREADS + tid;

    for (int t = 0; t < NTILES; t++) {
        if (t) {
            if (t >= NTILES - 1) { CP_WAIT0(); } else { CP_WAIT1(); }
            __syncthreads();
        }

        const uint32_t* Bbuf = reinterpret_cast<const uint32_t*>(
            sm + ((t & 1) ? SM_B1 : SM_B0));

        float acc[2][8][4];
#pragma unroll
        for (int mf = 0; mf < 2; mf++)
#pragma unroll
            for (int nf = 0; nf < 8; nf++)
#pragma unroll
                for (int j = 0; j < 4; j++) acc[mf][nf][j] = 0.f;

#pragma unroll
        for (int kc = 0; kc < 4; kc++) {
            const int ki = (kc * 8 + tq) ^ swg;
#pragma unroll
            for (int nf = 0; nf < 8; nf++) {
                const uint32_t* rowp = Bbuf + (cg * 64 + nf * 8 + g) * 32;
                uint32_t b0 = rowp[ki];
                uint32_t b1 = rowp[ki ^ 4];
#pragma unroll
                for (int mf = 0; mf < 2; mf++)
                    mma16(acc[mf][nf], ah[mf][kc], b0, b1);
            }
        }

        // epilogue: running row-max of acc (tq-merged), static predicated appends
#pragma unroll
        for (int ri = 0; ri < 4; ri++) {
            const int mf = ri >> 1, jb = (ri & 1) * 2;
            float tmax = acc[mf][0][jb];
            tmax = fmaxf(tmax, acc[mf][0][jb + 1]);
#pragma unroll
            for (int nf = 1; nf < 8; nf++) {
                tmax = fmaxf(tmax, acc[mf][nf][jb]);
                tmax = fmaxf(tmax, acc[mf][nf][jb + 1]);
            }
            tmax = fmaxf(tmax, __shfl_xor_sync(0xFFFFFFFFu, tmax, 1));
            tmax = fmaxf(tmax, __shfl_xor_sync(0xFFFFFFFFu, tmax, 2));
            bs[ri] = fmaxf(bs[ri], tmax);
            const float thr = bs[ri] - tauS[ri];
#pragma unroll
            for (int nf = 0; nf < 8; nf++) {
#pragma unroll
                for (int jj = 0; jj < 2; jj++) {
                    float av = acc[mf][nf][jb + jj];    // static indices only
                    if (av > thr) {
                        if (cnt < CAPT) {
                            clist[(size_t)cnt * NTHREADS] = (unsigned short)
                                ((t << 6) | (ri << 4) | (nf * 2 + jj));
                            cacc[(size_t)cnt * NTHREADS] = av;
                        }
                        cnt++;
                    }
                }
            }
        }

        __syncthreads();

        if (t + 2 < NTILES) {
            const uint32_t dbase = smb + ((t & 1) ? SM_B1 : SM_B0);
            const char* src = EBF + (size_t)(t + 2) * 16384;
#pragma unroll
            for (int i = 0; i < 4; i++) {
                int c = tid + i * 256;
                cp16(dbase + c * 16, src + c * 16);
            }
            CP_COMMIT();
        }
    }
    g_ccnt[blockIdx.x * NTHREADS + tid] = cnt;

    // final per-row threshold: merge bs across the two cg warps
    if (tq == 0 && cg == 0) {
#pragma unroll
        for (int ri = 0; ri < 4; ri++) {
            int rowL = rw * 32 + (ri >> 1) * 16 + g + (ri & 1) * 8;
            RVV[rowL] = bs[ri];
        }
    }
    __syncthreads();
    if (tq == 0 && cg == 1) {
#pragma unroll
        for (int ri = 0; ri < 4; ri++) {
            int rowL = rw * 32 + (ri >> 1) * 16 + g + (ri & 1) * 8;
            g_thr[rowBase + rowL] = fmaxf(bs[ri], RVV[rowL]) - tauS[ri];
        }
    }
}

// ---------------------------------------------------------------------------
// Kernel 3: PASS 2 — filter by final threshold, exact rescoring (R1 chain),
// per-row argmin via packed (d2,col) smem atomicMin (tie -> lowest col)
// ---------------------------------------------------------------------------
__global__ __launch_bounds__(256) void vq_pass2(
    const float* __restrict__ Z, const float* __restrict__ E)
{
    __shared__ float Zsh[BM * DDIM];     // 32 KB
    __shared__ float ZSQ2[BM];
    __shared__ float THR[BM];
    __shared__ ull   best[BM];

    const int b   = blockIdx.x;
    const int tid = threadIdx.x;
    const int warp = tid >> 5;
    const int cg   = warp & 1;
    const int rw   = warp >> 1;
    const int g    = (tid & 31) >> 2;
    const int tq   = tid & 3;

    // stage Z slab
    {
        const float4* zp = reinterpret_cast<const float4*>(Z + (size_t)b * BM * DDIM);
#pragma unroll
        for (int i = 0; i < 8; i++) {
            int c = tid + i * 256;
            reinterpret_cast<float4*>(Zsh)[c] = zp[c];
        }
    }
    if (tid < BM) {
        best[tid] = 0xFFFFFFFFFFFFFFFFull;
        THR[tid]  = g_thr[b * BM + tid];
    }
    __syncthreads();

    if (tid < BM) {
        float s = 0.f;
#pragma unroll
        for (int d = 0; d < DDIM; d++) {
            float v = Zsh[tid * DDIM + d];
            s = fmaf(v, v, s);
        }
        ZSQ2[tid] = s;
    }
    __syncthreads();

    const unsigned cnt = g_ccnt[b * NTHREADS + tid];
    const unsigned short* clist = g_clist + (size_t)b * CAPT * NTHREADS + tid;
    const float*          cacc  = g_cacc  + (size_t)b * CAPT * NTHREADS + tid;

    if (cnt <= CAPT) {
        for (unsigned s = 0; s < cnt; s++) {
            unsigned e = clist[(size_t)s * NTHREADS];
            float   av = cacc[(size_t)s * NTHREADS];
            int ri = (e >> 4) & 3;
            int rowL = rw * 32 + (ri >> 1) * 16 + g + (ri & 1) * 8;
            if (av > THR[rowL]) {
                int t  = e >> 6;
                int q  = e & 15;
                int col  = t * BN + cg * 64 + (q >> 1) * 8 + 2 * tq + (q & 1);
                const float* zr = Zsh + rowL * DDIM;
                const float4* ep = reinterpret_cast<const float4*>(
                    E + (size_t)col * DDIM);
                float dot = 0.f;
#pragma unroll
                for (int qq = 0; qq < 16; qq++) {
                    float4 e4 = ep[qq];
                    dot = fmaf(zr[qq * 4 + 0], e4.x, dot);
                    dot = fmaf(zr[qq * 4 + 1], e4.y, dot);
                    dot = fmaf(zr[qq * 4 + 2], e4.z, dot);
                    dot = fmaf(zr[qq * 4 + 3], e4.w, dot);
                }
                float tt = fmaf(-2.0f, dot, ZSQ2[rowL]);
                float d2 = tt + g_esq[col];                 // exact R1 chain
                ull pk = ((ull)__float_as_uint(d2) << 32) | (unsigned)col;
                atomicMin(&best[rowL], pk);
            }
        }
    } else {
        // overflow fallback: exact scan of this thread's 4 rows (never expected)
#pragma unroll
        for (int ri = 0; ri < 4; ri++) {
            int rowL = rw * 32 + (ri >> 1) * 16 + g + (ri & 1) * 8;
            const float* zr = Zsh + rowL * DDIM;
            for (int col = 0; col < KEMB; col++) {
                const float4* ep = reinterpret_cast<const float4*>(
                    E + (size_t)col * DDIM);
                float dot = 0.f;
#pragma unroll
                for (int qq = 0; qq < 16; qq++) {
                    float4 e4 = ep[qq];
                    dot = fmaf(zr[qq * 4 + 0], e4.x, dot);
                    dot = fmaf(zr[qq * 4 + 1], e4.y, dot);
                    dot = fmaf(zr[qq * 4 + 2], e4.z, dot);
                    dot = fmaf(zr[qq * 4 + 3], e4.w, dot);
                }
                float tt = fmaf(-2.0f, dot, ZSQ2[rowL]);
                float d2 = tt + g_esq[col];
                ull pk = ((ull)__float_as_uint(d2) << 32) | (unsigned)col;
                atomicMin(&best[rowL], pk);
            }
        }
    }
    __syncthreads();
    if (tid < BM) g_idx[b * BM + tid] = (int)(unsigned)best[tid];
}

// ---------------------------------------------------------------------------
// Kernel 4: gather + partial loss + index-as-float
// ---------------------------------------------------------------------------
__global__ __launch_bounds__(256) void gather_loss_kernel(
    const float* __restrict__ Z, const float* __restrict__ E,
    float* __restrict__ out)
{
    __shared__ float red[256];
    const int tid  = threadIdx.x;
    const int gtid = blockIdx.x * blockDim.x + tid;

    float lsum = 0.f;
    const float4* Z4 = reinterpret_cast<const float4*>(Z);
    float4* O4 = reinterpret_cast<float4*>(out);

#pragma unroll
    for (int j = 0; j < 4; j++) {
        int f   = gtid * 4 + j;
        int row = f >> 4;
        int dc  = (f & 15);
        int idx = g_idx[row];
        const float4* E4 = reinterpret_cast<const float4*>(E + (size_t)idx * DDIM);
        float4 q = E4[dc];
        float4 z = Z4[f];
        O4[f] = q;
        float dx = z.x - q.x, dy = z.y - q.y, dz = z.z - q.z, dw = z.w - q.w;
        lsum += dx * dx + dy * dy + dz * dz + dw * dw;
    }

    if (gtid < NROWS) out[OUT_IDX + gtid] = (float)g_idx[gtid];

    red[tid] = lsum;
    __syncthreads();
    for (int s = 128; s > 0; s >>= 1) {
        if (tid < s) red[tid] += red[tid + s];
        __syncthreads();
    }
    if (tid == 0) g_partial[blockIdx.x] = red[0];
}

// ---------------------------------------------------------------------------
// Kernel 5: finalize losses
// ---------------------------------------------------------------------------
__global__ __launch_bounds__(512) void finalize_kernel(float* __restrict__ out) {
    __shared__ float red[512];
    int tid = threadIdx.x;
    red[tid] = g_partial[tid] + g_partial[tid + 512];
    __syncthreads();
    for (int s = 256; s > 0; s >>= 1) {
        if (tid < s) red[tid] += red[tid + s];
        __syncthreads();
    }
    if (tid == 0) {
        float loss = red[0] * (1.0f / (float)(NROWS * DDIM)); // N*D = 2^22, exact
        out[OUT_LOSS + 0] = loss;
        out[OUT_LOSS + 1] = loss;
    }
}

// ---------------------------------------------------------------------------
extern "C" void kernel_launch(void* const* d_in, const int* in_sizes, int n_in,
                              void* d_out, int out_size)
{
    const float* Z = (const float*)d_in[0];
    const float* E = (const float*)d_in[1];
    if (n_in >= 2 && in_sizes[0] == KEMB * DDIM && in_sizes[1] == NROWS * DDIM) {
        const float* t = Z; Z = E; E = t;
    }
    float* out = (float*)d_out;

    cudaFuncSetAttribute(vq_pass1,
                         cudaFuncAttributeMaxDynamicSharedMemorySize, SMEM_TOTAL);

    esq_kernel<<<KEMB / 256, 256>>>(E);
    esplit_kernel<<<KEMB / 256, 256>>>(E);
    vq_pass1<<<NCTAS, NTHREADS, SMEM_TOTAL>>>(Z);
    vq_pass2<<<NCTAS, 256>>>(Z, E);
    gather_loss_kernel<<<NPARTIAL, 256>>>(Z, E, out);
    finalize_kernel<<<1, 512>>>(out);
}